// round 4
// baseline (speedup 1.0000x reference)
#include <cuda_runtime.h>

#define NTHREADS 256
#define ROWS 32
#define TS 1032            // tile row stride (floats, float4-aligned, padded)
#define HS 68              // hbuf row stride (float4-aligned)
#define WBLK 2176          // per-block stride in bufA (w1 uses 2048, hbuf uses 32*68=2176)
#define SSTRIDE 37         // transpose staging stride
#define SMAT 1184          // 32*37 floats per-warp staging

typedef unsigned long long u64;

__device__ __forceinline__ u64 pack2(float lo, float hi) {
    u64 r; asm("mov.b64 %0, {%1, %2};" : "=l"(r) : "f"(lo), "f"(hi)); return r;
}
__device__ __forceinline__ void unpack2(u64 v, float& lo, float& hi) {
    asm("mov.b64 {%0, %1}, %2;" : "=f"(lo), "=f"(hi) : "l"(v));
}
__device__ __forceinline__ u64 fma2(u64 a, u64 b, u64 c) {
    u64 d; asm("fma.rn.f32x2 %0, %1, %2, %3;" : "=l"(d) : "l"(a), "l"(b), "l"(c)); return d;
}

// smem layout (floats)
#define SM_TILE 0
#define SM_BUFA 33024                  // 32*1032
#define SM_W2   (SM_BUFA + 9472)       // bufA = max(4*2176, 8*1184) = 9472
#define SM_B1   (SM_W2 + 8192)
#define SM_B2   (SM_B1 + 256)
#define SM_TOTAL (SM_B2 + 128)         // 51072 floats = 204288 B

// warp-local 32x32 transpose of each row's 1024 cols: row'[32b+a] = row[32a+b]
__device__ __forceinline__ void transpose_tile(float* tile, float* stg, int warp, int lane) {
    float* S = stg + warp * SMAT;
    #pragma unroll
    for (int chunk = 0; chunk < 4; ++chunk) {
        float* row = tile + (chunk * 8 + warp) * TS;
        #pragma unroll
        for (int m = 0; m < 8; ++m) {
            int c0 = (m * 32 + lane) * 4;
            float4 v = *(const float4*)(row + c0);
            float* sp = S + (c0 >> 5) * SSTRIDE + (c0 & 31);
            sp[0] = v.x; sp[1] = v.y; sp[2] = v.z; sp[3] = v.w;
        }
        __syncwarp();
        #pragma unroll
        for (int m = 0; m < 8; ++m) {
            int c0 = (m * 32 + lane) * 4;
            const float* sp = S + (c0 & 31) * SSTRIDE + (c0 >> 5);
            float4 v;
            v.x = sp[0 * SSTRIDE]; v.y = sp[1 * SSTRIDE];
            v.z = sp[2 * SSTRIDE]; v.w = sp[3 * SSTRIDE];
            *(float4*)(row + c0) = v;
        }
        __syncwarp();
    }
}

__global__ __launch_bounds__(NTHREADS, 1) void mixer_kernel(
    const float* __restrict__ x,
    const float* __restrict__ W1a, const float* __restrict__ B1a,
    const float* __restrict__ W2a, const float* __restrict__ B2a,
    const float* __restrict__ W1b, const float* __restrict__ B1b,
    const float* __restrict__ W2b, const float* __restrict__ B2b,
    float* __restrict__ out)
{
    extern __shared__ float smem[];
    float* tile = smem + SM_TILE;
    float* bufA = smem + SM_BUFA;
    float* w2s  = smem + SM_W2;
    float* b1s  = smem + SM_B1;
    float* b2s  = smem + SM_B2;

    const int tid   = threadIdx.x;
    const int warp  = tid >> 5;
    const int lane  = tid & 31;
    const int nb    = warp >> 1;           // block within group (0..3)
    const int rhalf = warp & 1;
    const int rg    = lane >> 3;
    const int hg    = lane & 7;
    const int rbase = rhalf * 16 + rg * 4; // 4 rows per thread
    const long row0 = (long)blockIdx.x * ROWS;

    // ---- load x tile (float4 all the way) ----
    {
        const float4* src = (const float4*)(x + row0 * 1024);
        #pragma unroll
        for (int it = 0; it < 32; ++it) {
            int i = tid + it * NTHREADS;
            int r = i >> 8, c4 = i & 255;
            *(float4*)(tile + r * TS + c4 * 4) = src[r * 256 + c4];
        }
    }

    const float* W1p[2] = {W1a, W1b};
    const float* W2p[2] = {W2a, W2b};
    const float* B1p[2] = {B1a, B1b};
    const float* B2p[2] = {B2a, B2b};

    float4 pf1[8], pf2[8];

    for (int gi = 0; gi < 16; ++gi) {
        const int layer = gi >> 3;
        const int g     = gi & 7;

        if (gi == 8) {                 // mix layers: transpose tile in smem
            __syncthreads();
            transpose_tile(tile, bufA, warp, lane);
        }
        __syncthreads();               // everyone done with bufA/w2s of prev group

        // ---- stage weights for this group ----
        if (gi == 0) {
            const float4* s1 = (const float4*)W1p[0];
            const float4* s2 = (const float4*)W2p[0];
            #pragma unroll
            for (int j = 0; j < 8; ++j) {
                int idx = tid + 256 * j;
                int blk = idx >> 9, off = idx & 511;
                ((float4*)(bufA + blk * WBLK))[off] = s1[idx];
                ((float4*)w2s)[idx] = s2[idx];
            }
        } else {
            #pragma unroll
            for (int j = 0; j < 8; ++j) {
                int idx = tid + 256 * j;
                int blk = idx >> 9, off = idx & 511;
                ((float4*)(bufA + blk * WBLK))[off] = pf1[j];
                ((float4*)w2s)[idx] = pf2[j];
            }
        }
        b1s[tid] = B1p[layer][g * 256 + tid];
        if (tid < 128) b2s[tid] = B2p[layer][g * 128 + tid];
        __syncthreads();

        // ---- prefetch next group's weights (hidden behind compute) ----
        if (gi < 15) {
            const int l2 = (gi + 1) >> 3;
            const int g2 = (gi + 1) & 7;
            const float4* n1 = (const float4*)(W1p[l2] + (size_t)g2 * 8192);
            const float4* n2 = (const float4*)(W2p[l2] + (size_t)g2 * 8192);
            #pragma unroll
            for (int j = 0; j < 8; ++j) {
                pf1[j] = n1[tid + 256 * j];
                pf2[j] = n2[tid + 256 * j];
            }
        }

        const int n     = g * 4 + nb;
        const int cbase = n * 32;

        // ---- matmul1: 4 rows x 8 hidden (cols 4*hg+32*j), all LDS.128 ----
        u64 a1[4][2][2];
        {
            const float* bp = b1s + nb * 64 + 4 * hg;
            u64 b00 = *(const u64*)(bp + 0);
            u64 b01 = *(const u64*)(bp + 2);
            u64 b10 = *(const u64*)(bp + 32);
            u64 b11 = *(const u64*)(bp + 34);
            #pragma unroll
            for (int i = 0; i < 4; ++i) {
                a1[i][0][0] = b00; a1[i][0][1] = b01;
                a1[i][1][0] = b10; a1[i][1][1] = b11;
            }
        }
        {
            const float* w1p  = bufA + nb * WBLK + 4 * hg;
            const float* xrow = tile + rbase * TS + cbase;
            #pragma unroll
            for (int kq = 0; kq < 8; ++kq) {
                float xa[4][4];
                #pragma unroll
                for (int i = 0; i < 4; ++i)
                    *(float4*)xa[i] = *(const float4*)(xrow + i * TS + 4 * kq);
                #pragma unroll
                for (int t = 0; t < 4; ++t) {
                    const float* wk = w1p + (4 * kq + t) * 64;
                    ulonglong2 wA = *(const ulonglong2*)(wk);
                    ulonglong2 wB = *(const ulonglong2*)(wk + 32);
                    #pragma unroll
                    for (int i = 0; i < 4; ++i) {
                        u64 xp = pack2(xa[i][t], xa[i][t]);
                        a1[i][0][0] = fma2(xp, wA.x, a1[i][0][0]);
                        a1[i][0][1] = fma2(xp, wA.y, a1[i][0][1]);
                        a1[i][1][0] = fma2(xp, wB.x, a1[i][1][0]);
                        a1[i][1][1] = fma2(xp, wB.y, a1[i][1][1]);
                    }
                }
            }
        }
        asm volatile("bar.sync %0, %1;" :: "r"(nb + 1), "r"(64) : "memory");

        // ---- ELU + stage h (float4 stores) ----
        {
            float* hb = bufA + nb * WBLK + 4 * hg;
            #pragma unroll
            for (int i = 0; i < 4; ++i) {
                #pragma unroll
                for (int j = 0; j < 2; ++j) {
                    float e0, e1, e2, e3;
                    unpack2(a1[i][j][0], e0, e1);
                    unpack2(a1[i][j][1], e2, e3);
                    float4 hv;
                    hv.x = e0 > 0.f ? e0 : (__expf(e0) - 1.f);
                    hv.y = e1 > 0.f ? e1 : (__expf(e1) - 1.f);
                    hv.z = e2 > 0.f ? e2 : (__expf(e2) - 1.f);
                    hv.w = e3 > 0.f ? e3 : (__expf(e3) - 1.f);
                    *(float4*)(hb + (rbase + i) * HS + 32 * j) = hv;
                }
            }
        }
        asm volatile("bar.sync %0, %1;" :: "r"(nb + 1), "r"(64) : "memory");

        // ---- matmul2: 4 rows x 4 out cols (cols 4*cg), all LDS.128 ----
        {
            const int cg = hg;
            const float* hrd = bufA + nb * WBLK + rbase * HS;
            const float* w2p = w2s + nb * 2048 + 4 * cg;
            u64 a2[4][2];
            {
                const float* bp2 = b2s + nb * 32 + 4 * cg;
                u64 bv0 = *(const u64*)(bp2);
                u64 bv1 = *(const u64*)(bp2 + 2);
                const u64 ONEpk = pack2(1.f, 1.f);
                #pragma unroll
                for (int i = 0; i < 4; ++i) {
                    float4 rv = *(const float4*)(tile + (rbase + i) * TS + cbase + 4 * cg);
                    a2[i][0] = fma2(ONEpk, bv0, pack2(rv.x, rv.y));
                    a2[i][1] = fma2(ONEpk, bv1, pack2(rv.z, rv.w));
                }
            }
            #pragma unroll
            for (int kq = 0; kq < 16; ++kq) {
                float ha[4][4];
                #pragma unroll
                for (int i = 0; i < 4; ++i)
                    *(float4*)ha[i] = *(const float4*)(hrd + i * HS + 4 * kq);
                #pragma unroll
                for (int t = 0; t < 4; ++t) {
                    ulonglong2 wv = *(const ulonglong2*)(w2p + (4 * kq + t) * 32);
                    #pragma unroll
                    for (int i = 0; i < 4; ++i) {
                        u64 hp = pack2(ha[i][t], ha[i][t]);
                        a2[i][0] = fma2(hp, wv.x, a2[i][0]);
                        a2[i][1] = fma2(hp, wv.y, a2[i][1]);
                    }
                }
            }
            #pragma unroll
            for (int i = 0; i < 4; ++i) {
                float4 o;
                unpack2(a2[i][0], o.x, o.y);
                unpack2(a2[i][1], o.z, o.w);
                *(float4*)(tile + (rbase + i) * TS + cbase + 4 * cg) = o;
            }
        }
    }

    __syncthreads();
    transpose_tile(tile, bufA, warp, lane);   // undo layer-1 permutation
    __syncthreads();

    // ---- store output (coalesced float4) ----
    {
        float4* dst = (float4*)(out + row0 * 1024);
        #pragma unroll
        for (int it = 0; it < 32; ++it) {
            int i = tid + it * NTHREADS;
            int r = i >> 8, c4 = i & 255;
            dst[r * 256 + c4] = *(const float4*)(tile + r * TS + c4 * 4);
        }
    }
}

extern "C" void kernel_launch(void* const* d_in, const int* in_sizes, int n_in,
                              void* d_out, int out_size) {
    const float* x   = (const float*)d_in[0];
    const float* W1a = (const float*)d_in[1];
    const float* B1a = (const float*)d_in[2];
    const float* W2a = (const float*)d_in[3];
    const float* B2a = (const float*)d_in[4];
    const float* W1b = (const float*)d_in[5];
    const float* B1b = (const float*)d_in[6];
    const float* W2b = (const float*)d_in[7];
    const float* B2b = (const float*)d_in[8];
    float* out = (float*)d_out;

    int rows = in_sizes[0] / 1024;
    int grid = rows / ROWS;                  // 512

    size_t smem_bytes = (size_t)SM_TOTAL * sizeof(float);   // ~204 KB
    static int configured = -1;
    if (configured < 0) {
        cudaFuncSetAttribute(mixer_kernel,
                             cudaFuncAttributeMaxDynamicSharedMemorySize,
                             (int)smem_bytes);
        configured = 1;
    }

    mixer_kernel<<<grid, NTHREADS, smem_bytes>>>(
        x, W1a, B1a, W2a, B2a, W1b, B1b, W2b, B2b, out);
}